// round 13
// baseline (speedup 1.0000x reference)
#include <cuda_runtime.h>
#include <cstdint>
#include <cstddef>

#define F 128
#define MAXN 500000
#define CAP 64       // bucket capacity per row (Poisson(1): overflow prob ~0)

// -------- scratch (device globals; no allocation allowed) --------
__device__ float d_bufA[(size_t)MAXN * F];        // 256 MB
__device__ float d_bufB[(size_t)MAXN * F];        // 256 MB
__device__ int   d_csr[(size_t)MAXN * CAP];       // 128 MB padded buckets
__device__ int   d_cnt[MAXN];                     // row degrees
__device__ float d_s[MAXN];
__device__ float d_gsum[F];
__device__ __align__(16) float d_el[4];
__device__ __align__(16) uint32_t d_wf1[32768];   // W1 fragments: [H 16384 | L 16384]
__device__ __align__(16) uint32_t d_wf2[32768];   // W2 fragments

// -------- tf32 helpers --------
static __device__ __forceinline__ uint32_t f2tf32(float f) {
    uint32_t r;
    asm("cvt.rna.tf32.f32 %0, %1;" : "=r"(r) : "f"(f));
    return r;
}
// D(16x8,f32) += A(16x8,tf32 row) * B(8x8,tf32 col)
static __device__ __forceinline__ void mma_tf32(float* c, const uint4& a, const uint2& b) {
    asm("mma.sync.aligned.m16n8k8.row.col.f32.tf32.tf32.f32 "
        "{%0,%1,%2,%3}, {%4,%5,%6,%7}, {%8,%9}, {%0,%1,%2,%3};"
        : "+f"(c[0]), "+f"(c[1]), "+f"(c[2]), "+f"(c[3])
        : "r"(a.x), "r"(a.y), "r"(a.z), "r"(a.w), "r"(b.x), "r"(b.y));
}

// -------- zero counters --------
__global__ void zero_kernel() {
    int i = blockIdx.x * blockDim.x + threadIdx.x;
    if (i < MAXN) d_cnt[i] = 0;
    if (i < F) d_gsum[i] = 0.f;
}

// -------- bucket fill: csr[row][p++] = col --------
__global__ void fill_kernel(const int* __restrict__ ei, int E) {
    int e = blockIdx.x * blockDim.x + threadIdx.x;
    if (e < E) {
        int r = ei[e];
        int p = atomicAdd(&d_cnt[r], 1);
        if (p < CAP) d_csr[((size_t)r << 6) + p] = ei[E + e];
    }
}

// -------- per-position norm: s[i] = dis[row[i]] * dis[col[i]] --------
__global__ void s_kernel(const int* __restrict__ ei, int n, int E) {
    int i = blockIdx.x * blockDim.x + threadIdx.x;
    if (i < n) {
        float dr = (float)d_cnt[ei[i]];
        float dc = (float)d_cnt[ei[E + i]];
        float a = dr > 0.f ? rsqrtf(dr) : 0.f;
        float b = dc > 0.f ? rsqrtf(dc) : 0.f;
        d_s[i] = a * b;
    }
}

// -------- one-time W -> fragment-layout transform (grid 8 x 512) --------
//   idx = ((nc*16+ks)*32+lp)*2 + sb;  H at dst[idx], L at dst[16384+idx]
__global__ void wprep_kernel(const float* __restrict__ W, uint32_t* __restrict__ dst) {
    int lin = blockIdx.x * 512 + threadIdx.x;   // 0..4095
    int k = lin >> 5, q = lin & 31;
    float4 wv4 = *(const float4*)(W + k * F + q * 4);
    int ks = k >> 3, kk = k & 7;
    int btig = kk & 3, sb = kk >> 2;
    int sw = ks & 7;
    float wv[4] = { wv4.x, wv4.y, wv4.z, wv4.w };
    #pragma unroll
    for (int j = 0; j < 4; j++) {
        int c = q * 4 + j;
        int nc = c >> 3, cg = c & 7;
        int lp = (cg * 4 + btig) ^ sw;
        int idx = ((nc * 16 + ks) * 32 + lp) * 2 + sb;
        uint32_t wh = f2tf32(wv[j]);
        float rem = wv[j] - __uint_as_float(wh);
        dst[idx] = wh;
        dst[16384 + idx] = f2tf32(rem);
    }
}

// -------- fused tensor-core GEMM --------
// gathered=0: out[i] = (X[i] @ W + b) * s[i]
// gathered=1: out[i] = (relu(sum_{c in bucket(i)} X[c]) @ W + b) * s[i]
//   (the conv1->conv2 scatter aggregation fused into A-staging: no 256MB
//    intermediate materialize/reload. Warp per row, lanes = 32 float4 ch.)
// Block 128x128, K=128, 256 threads (8 warps, 2x4 warp grid, warp tile 64x32).
// A fragments staged in smem (64KB); B fragments (Wh+Wl, wprep-precomputed)
// read directly from global (L2-resident). 2 blocks/SM.
// Fragment maps (PTX m16n8k8.tf32): g=lane>>2, tig=lane&3;
//   A: a0=A[g][tig] a1=A[g+8][tig] a2=A[g][tig+4] a3=A[g+8][tig+4]
//   B: b0=B[tig][col_g] b1=B[tig+4][col_g]
//   D: c0=D[g][2tig] c1=D[g][2tig+1] c2=D[g+8][2tig] c3=D[g+8][2tig+1]
#define GSM_BYTES 65536   // A fragments only: 8 mc x 16 ks x 32 lanes x 4 u32

__global__ __launch_bounds__(256, 2)
void gemm_kernel(const float* __restrict__ X, const uint32_t* __restrict__ wf,
                 const float* __restrict__ bias,
                 float* __restrict__ out, int n, int gathered) {
    extern __shared__ float smf[];
    uint32_t* smu = (uint32_t*)smf;
    const int tid = threadIdx.x;
    const int w = tid >> 5, l = tid & 31;
    const int wm = w >> 2, wn = w & 3;
    const int g = l >> 2, tig = l & 3;
    const int rbase = blockIdx.x * 128;

    // ---- stage A fragments: per it, warp w owns row it*8+w, lanes = q
    #pragma unroll
    for (int it = 0; it < 16; it++) {
        int r = it * 8 + w;
        int q = l;
        int row = rbase + r;
        float4 v = make_float4(0.f, 0.f, 0.f, 0.f);
        if (!gathered) {
            if (row < n) v = ((const float4*)(X + (size_t)row * F))[q];
        } else if (row < n) {
            int cnt = d_cnt[row]; if (cnt > CAP) cnt = CAP;
            size_t base = (size_t)row << 6;
            for (int i = 0; i < cnt; i++) {
                int c = d_csr[base + i];
                float4 t = ((const float4*)(X + (size_t)c * F))[q];
                v.x += t.x; v.y += t.y; v.z += t.z; v.w += t.w;
            }
            v.x = fmaxf(v.x, 0.f); v.y = fmaxf(v.y, 0.f);
            v.z = fmaxf(v.z, 0.f); v.w = fmaxf(v.w, 0.f);
        }
        int mc = r >> 4, gp = r & 15, gg = gp & 7;
        int ks = q >> 1;
        int slot = ((q & 1) << 1) + (gp >> 3);     // {a0,a1,a2,a3} position
        int base16 = (mc * 16 + ks) * 32;
        int sw = ks & 7;
        float vv[4] = { v.x, v.y, v.z, v.w };
        #pragma unroll
        for (int j = 0; j < 4; j++) {
            int lp = (gg * 4 + j) ^ sw;            // j = tig of element k0+j
            smu[(base16 + lp) * 4 + slot] = f2tf32(vv[j]);
        }
    }
    __syncthreads();

    // ---- mainloop: warp tile 64x32 = 4 m-tiles x 4 n-tiles
    float acc[4][4][4];
    #pragma unroll
    for (int mt = 0; mt < 4; mt++)
        #pragma unroll
        for (int nt = 0; nt < 4; nt++)
            #pragma unroll
            for (int j = 0; j < 4; j++) acc[mt][nt][j] = 0.f;

    #pragma unroll 4
    for (int ks = 0; ks < 16; ks++) {
        int lp = l ^ (ks & 7);
        uint4 af[4];
        #pragma unroll
        for (int mt = 0; mt < 4; mt++)
            af[mt] = *(const uint4*)&smu[(((wm * 4 + mt) * 16 + ks) * 32 + lp) * 4];
        uint2 bh[4], bl[4];
        #pragma unroll
        for (int nt = 0; nt < 4; nt++) {
            int bidx = (((wn * 4 + nt) * 16 + ks) * 32 + lp) * 2;
            bh[nt] = *(const uint2*)&wf[bidx];
            bl[nt] = *(const uint2*)&wf[16384 + bidx];
        }
        #pragma unroll
        for (int mt = 0; mt < 4; mt++)
            #pragma unroll
            for (int nt = 0; nt < 4; nt++) {
                mma_tf32(acc[mt][nt], af[mt], bh[nt]);
                mma_tf32(acc[mt][nt], af[mt], bl[nt]);
            }
    }

    // ---- epilogue: bias + degree-norm scale, write fp32
    #pragma unroll
    for (int mt = 0; mt < 4; mt++) {
        int row_lo = rbase + wm * 64 + mt * 16 + g;
        int row_hi = row_lo + 8;
        float s_lo = (row_lo < n) ? d_s[row_lo] : 0.f;
        float s_hi = (row_hi < n) ? d_s[row_hi] : 0.f;
        #pragma unroll
        for (int nt = 0; nt < 4; nt++) {
            int col = wn * 32 + nt * 8 + tig * 2;
            float b0 = bias[col], b1 = bias[col + 1];
            if (row_lo < n) {
                float2 o = make_float2((acc[mt][nt][0] + b0) * s_lo,
                                       (acc[mt][nt][1] + b1) * s_lo);
                *(float2*)(out + (size_t)row_lo * F + col) = o;
            }
            if (row_hi < n) {
                float2 o = make_float2((acc[mt][nt][2] + b0) * s_hi,
                                       (acc[mt][nt][3] + b1) * s_hi);
                *(float2*)(out + (size_t)row_hi * F + col) = o;
            }
        }
    }
}

// -------- gather + relu + column-sum fusion (never materializes agg2) --------
__global__ void gather_mean_kernel(const float* __restrict__ src, int n) {
    __shared__ float smr[128];
    int t = threadIdx.x;
    if (t < 128) smr[t] = 0.f;
    __syncthreads();
    int warp = (blockIdx.x * blockDim.x + t) >> 5;
    int lane = t & 31;
    int nw = (gridDim.x * blockDim.x) >> 5;
    float4 ps = make_float4(0.f, 0.f, 0.f, 0.f);
    for (int r = warp; r < n; r += nw) {
        int cnt = d_cnt[r]; if (cnt > CAP) cnt = CAP;
        float4 acc = make_float4(0.f, 0.f, 0.f, 0.f);
        size_t base = (size_t)r << 6;
        for (int i = 0; i < cnt; i++) {
            int c = d_csr[base + i];
            float4 v = ((const float4*)(src + (size_t)c * F))[lane];
            acc.x += v.x; acc.y += v.y; acc.z += v.z; acc.w += v.w;
        }
        ps.x += fmaxf(acc.x, 0.f); ps.y += fmaxf(acc.y, 0.f);
        ps.z += fmaxf(acc.z, 0.f); ps.w += fmaxf(acc.w, 0.f);
    }
    atomicAdd(&smr[lane * 4 + 0], ps.x);
    atomicAdd(&smr[lane * 4 + 1], ps.y);
    atomicAdd(&smr[lane * 4 + 2], ps.z);
    atomicAdd(&smr[lane * 4 + 3], ps.w);
    __syncthreads();
    if (t < 128) atomicAdd(&d_gsum[t], smr[t]);
}

// -------- latent head (1 block, 128 threads) --------
__global__ void head_kernel(const float* __restrict__ eps,
                            const float* __restrict__ Wmu, const float* __restrict__ bmu,
                            const float* __restrict__ Wlv, const float* __restrict__ blv,
                            const float* __restrict__ Wn,  const float* __restrict__ bn,
                            const float* __restrict__ We1, const float* __restrict__ be1,
                            const float* __restrict__ We2, const float* __restrict__ be2,
                            float* __restrict__ out, int n, int E) {
    __shared__ float zs[32];
    __shared__ float ehs[128];
    int t = threadIdx.x;
    float invN = 1.0f / (float)n;
    size_t ofs = 16 + (size_t)E * 4;
    if (t < 32) {
        float mu = bmu[t], lv = blv[t];
        for (int c = 0; c < 128; c++) {
            float g = d_gsum[c] * invN;
            mu += g * Wmu[c * 32 + t];
            lv += g * Wlv[c * 32 + t];
        }
        zs[t] = mu + eps[t] * expf(0.5f * lv);
        out[ofs + t] = mu;
        out[ofs + 32 + t] = lv;
    }
    __syncthreads();
    if (t < 16) {
        float v = bn[t];
        for (int j = 0; j < 32; j++) v += zs[j] * Wn[j * 16 + t];
        out[t] = v;
    }
    {
        float v = be1[t];
        for (int k = 0; k < 64; k++) v += zs[k & 31] * We1[k * 128 + t];
        ehs[t] = fmaxf(v, 0.f);
    }
    __syncthreads();
    if (t < 4) {
        float v = be2[t];
        for (int h2 = 0; h2 < 128; h2++) v += ehs[h2] * We2[h2 * 4 + t];
        d_el[t] = v;
    }
}

// -------- broadcast identical edge logits --------
__global__ void bcast_kernel(float* __restrict__ out, int E) {
    int e = blockIdx.x * blockDim.x + threadIdx.x;
    float4 v = *(const float4*)d_el;
    if (e < E) ((float4*)(out + 16))[e] = v;
}

extern "C" void kernel_launch(void* const* d_in, const int* in_sizes, int n_in,
                              void* d_out, int out_size) {
    const float* x   = (const float*)d_in[0];
    const int*   ei  = (const int*)d_in[1];      // int32 (JAX x64 disabled)
    const float* eps = (const float*)d_in[2];
    const float* W1  = (const float*)d_in[3];
    const float* b1  = (const float*)d_in[4];
    const float* W2  = (const float*)d_in[5];
    const float* b2  = (const float*)d_in[6];
    const float* Wmu = (const float*)d_in[7];
    const float* bmu = (const float*)d_in[8];
    const float* Wlv = (const float*)d_in[9];
    const float* blv = (const float*)d_in[10];
    const float* Wn  = (const float*)d_in[11];
    const float* bn  = (const float*)d_in[12];
    const float* We1 = (const float*)d_in[13];
    const float* be1 = (const float*)d_in[14];
    const float* We2 = (const float*)d_in[15];
    const float* be2 = (const float*)d_in[16];
    float* out = (float*)d_out;

    int n = in_sizes[0] / F;       // 500000
    int E = in_sizes[1] / 2;       // 500000

    float* bufA_p = nullptr;
    float* bufB_p = nullptr;
    uint32_t* wf1_p = nullptr;
    uint32_t* wf2_p = nullptr;
    cudaGetSymbolAddress((void**)&bufA_p, d_bufA);
    cudaGetSymbolAddress((void**)&bufB_p, d_bufB);
    cudaGetSymbolAddress((void**)&wf1_p, d_wf1);
    cudaGetSymbolAddress((void**)&wf2_p, d_wf2);

    cudaFuncSetAttribute(gemm_kernel,
                         cudaFuncAttributeMaxDynamicSharedMemorySize, GSM_BYTES);

    int gblocks = (n + 127) / 128;

    zero_kernel<<<(MAXN + 255) / 256, 256>>>();
    fill_kernel<<<(E + 255) / 256, 256>>>(ei, E);
    s_kernel<<<(n + 255) / 256, 256>>>(ei, n, E);
    wprep_kernel<<<8, 512>>>(W1, wf1_p);
    wprep_kernel<<<8, 512>>>(W2, wf2_p);

    // conv1: bufA = (x@W1+b1)*s
    gemm_kernel<<<gblocks, 256, GSM_BYTES>>>(x, wf1_p, b1, bufA_p, n, 0);
    // conv2 (gather fused into staging): bufB = (relu(gather(bufA))@W2+b2)*s
    gemm_kernel<<<gblocks, 256, GSM_BYTES>>>(bufA_p, wf2_p, b2, bufB_p, n, 1);
    // fused gather+relu+colsum of conv2 output
    gather_mean_kernel<<<2048, 256>>>(bufB_p, n);

    // latent head ; edge-logit broadcast
    head_kernel<<<1, 128>>>(eps, Wmu, bmu, Wlv, blv, Wn, bn, We1, be1, We2, be2,
                            out, n, E);
    bcast_kernel<<<(E + 255) / 256, 256>>>(out, E);
}

// round 14
// speedup vs baseline: 1.1547x; 1.1547x over previous
#include <cuda_runtime.h>
#include <cstdint>
#include <cstddef>

#define F 128
#define MAXN 500000
#define CAP 64       // bucket capacity per row (Poisson(1): overflow prob ~0)

// -------- scratch (device globals; no allocation allowed) --------
__device__ float d_bufA[(size_t)MAXN * F];        // 256 MB
__device__ float d_bufB[(size_t)MAXN * F];        // 256 MB
__device__ int   d_csr[(size_t)MAXN * CAP];       // 128 MB padded buckets
__device__ int   d_cnt[MAXN];                     // row degrees
__device__ float d_s[MAXN];
__device__ float d_gsum[F];
__device__ __align__(16) float d_el[4];
__device__ __align__(16) uint32_t d_wf1[65536];   // W1 frags interleaved [H0,H1,L0,L1] per slot
__device__ __align__(16) uint32_t d_wf2[65536];   // W2 frags

// -------- tf32 helpers --------
static __device__ __forceinline__ uint32_t f2tf32(float f) {
    uint32_t r;
    asm("cvt.rna.tf32.f32 %0, %1;" : "=r"(r) : "f"(f));
    return r;
}
// D(16x8,f32) += A(16x8,tf32 row) * B(8x8,tf32 col)
static __device__ __forceinline__ void mma_tf32(float* c, const uint4& a, const uint2& b) {
    asm("mma.sync.aligned.m16n8k8.row.col.f32.tf32.tf32.f32 "
        "{%0,%1,%2,%3}, {%4,%5,%6,%7}, {%8,%9}, {%0,%1,%2,%3};"
        : "+f"(c[0]), "+f"(c[1]), "+f"(c[2]), "+f"(c[3])
        : "r"(a.x), "r"(a.y), "r"(a.z), "r"(a.w), "r"(b.x), "r"(b.y));
}

// -------- zero counters --------
__global__ void zero_kernel() {
    int i = blockIdx.x * blockDim.x + threadIdx.x;
    if (i < MAXN) d_cnt[i] = 0;
    if (i < F) d_gsum[i] = 0.f;
}

// -------- bucket fill: csr[row][p++] = col --------
__global__ void fill_kernel(const int* __restrict__ ei, int E) {
    int e = blockIdx.x * blockDim.x + threadIdx.x;
    if (e < E) {
        int r = ei[e];
        int p = atomicAdd(&d_cnt[r], 1);
        if (p < CAP) d_csr[((size_t)r << 6) + p] = ei[E + e];
    }
}

// -------- per-position norm: s[i] = dis[row[i]] * dis[col[i]] --------
__global__ void s_kernel(const int* __restrict__ ei, int n, int E) {
    int i = blockIdx.x * blockDim.x + threadIdx.x;
    if (i < n) {
        float dr = (float)d_cnt[ei[i]];
        float dc = (float)d_cnt[ei[E + i]];
        float a = dr > 0.f ? rsqrtf(dr) : 0.f;
        float b = dc > 0.f ? rsqrtf(dc) : 0.f;
        d_s[i] = a * b;
    }
}

// -------- one-time W -> fragment-layout transform (grid 8 x 512) --------
// Interleaved layout: fragIdx = ((nc*16+ks)*32+lp)*2 + sb encodes slot pair;
// here we store per 16B group: dst[frag*4 + sb] = H, dst[frag*4 + 2 + sb] = L
// with frag = ((nc*16+ks)*32+lp)  -> mainloop loads ONE uint4 per (nt,ks).
__global__ void wprep_kernel(const float* __restrict__ W, uint32_t* __restrict__ dst) {
    int lin = blockIdx.x * 512 + threadIdx.x;   // 0..4095
    int k = lin >> 5, q = lin & 31;
    float4 wv4 = *(const float4*)(W + k * F + q * 4);
    int ks = k >> 3, kk = k & 7;
    int btig = kk & 3, sb = kk >> 2;
    int sw = ks & 7;
    float wv[4] = { wv4.x, wv4.y, wv4.z, wv4.w };
    #pragma unroll
    for (int j = 0; j < 4; j++) {
        int c = q * 4 + j;
        int nc = c >> 3, cg = c & 7;
        int lp = (cg * 4 + btig) ^ sw;
        int frag = (nc * 16 + ks) * 32 + lp;
        uint32_t wh = f2tf32(wv[j]);
        float rem = wv[j] - __uint_as_float(wh);
        dst[frag * 4 + sb] = wh;
        dst[frag * 4 + 2 + sb] = f2tf32(rem);
    }
}

// -------- fused tensor-core GEMM: out[i] = (relu?(X[i]) @ W + b) * s[i] --------
// Block 128x128, K=128, 256 threads (8 warps, 2x4 warp grid, warp tile 64x32).
// A fragments staged in smem (64KB). B fragments (Wh+Wl interleaved,
// wprep-precomputed) read directly from global via ONE LDG.128 per (nt,ks)
// — halves LSU pressure vs split arrays; region is L2/L1-resident.
// 2 blocks/SM: phases of one block overlap the other's mainloop.
// Fragment maps (PTX m16n8k8.tf32): g=lane>>2, tig=lane&3;
//   A: a0=A[g][tig] a1=A[g+8][tig] a2=A[g][tig+4] a3=A[g+8][tig+4]
//   B: b0=B[tig][col_g] b1=B[tig+4][col_g]
//   D: c0=D[g][2tig] c1=D[g][2tig+1] c2=D[g+8][2tig] c3=D[g+8][2tig+1]
#define GSM_BYTES 65536   // A fragments only: 8 mc x 16 ks x 32 lanes x 4 u32

__global__ __launch_bounds__(256, 2)
void gemm_kernel(const float* __restrict__ X, const uint32_t* __restrict__ wf,
                 const float* __restrict__ bias,
                 float* __restrict__ out, int n, int relu_in) {
    extern __shared__ float smf[];
    uint32_t* smu = (uint32_t*)smf;
    const int tid = threadIdx.x;
    const int w = tid >> 5, l = tid & 31;
    const int wm = w >> 2, wn = w & 3;
    const int g = l >> 2, tig = l & 3;
    const int rbase = blockIdx.x * 128;

    // ---- stage A fragments: 4096 float4, 16 per thread
    #pragma unroll
    for (int it = 0; it < 16; it++) {
        int lin = it * 256 + tid;
        int r = lin >> 5, q = lin & 31;
        int row = rbase + r;
        float4 v = make_float4(0.f, 0.f, 0.f, 0.f);
        if (row < n) v = ((const float4*)(X + (size_t)row * F))[q];
        if (relu_in) {
            v.x = fmaxf(v.x, 0.f); v.y = fmaxf(v.y, 0.f);
            v.z = fmaxf(v.z, 0.f); v.w = fmaxf(v.w, 0.f);
        }
        int mc = r >> 4, gp = r & 15, gg = gp & 7;
        int ks = q >> 1;
        int slot = ((q & 1) << 1) + (gp >> 3);     // {a0,a1,a2,a3} position
        int base16 = (mc * 16 + ks) * 32;
        int sw = ks & 7;
        float vv[4] = { v.x, v.y, v.z, v.w };
        #pragma unroll
        for (int j = 0; j < 4; j++) {
            int lp = (gg * 4 + j) ^ sw;            // j = tig of element k0+j
            smu[(base16 + lp) * 4 + slot] = f2tf32(vv[j]);
        }
    }
    __syncthreads();

    // ---- mainloop: warp tile 64x32 = 4 m-tiles x 4 n-tiles
    float acc[4][4][4];
    #pragma unroll
    for (int mt = 0; mt < 4; mt++)
        #pragma unroll
        for (int nt = 0; nt < 4; nt++)
            #pragma unroll
            for (int j = 0; j < 4; j++) acc[mt][nt][j] = 0.f;

    #pragma unroll 4
    for (int ks = 0; ks < 16; ks++) {
        int lp = l ^ (ks & 7);
        uint4 af[4];
        #pragma unroll
        for (int mt = 0; mt < 4; mt++)
            af[mt] = *(const uint4*)&smu[(((wm * 4 + mt) * 16 + ks) * 32 + lp) * 4];
        uint4 bq[4];
        #pragma unroll
        for (int nt = 0; nt < 4; nt++) {
            int frag = ((wn * 4 + nt) * 16 + ks) * 32 + lp;
            bq[nt] = *(const uint4*)&wf[frag * 4];
        }
        #pragma unroll
        for (int mt = 0; mt < 4; mt++)
            #pragma unroll
            for (int nt = 0; nt < 4; nt++) {
                uint2 bh = make_uint2(bq[nt].x, bq[nt].y);
                uint2 bl = make_uint2(bq[nt].z, bq[nt].w);
                mma_tf32(acc[mt][nt], af[mt], bh);
                mma_tf32(acc[mt][nt], af[mt], bl);
            }
    }

    // ---- epilogue: bias + degree-norm scale, write fp32
    #pragma unroll
    for (int mt = 0; mt < 4; mt++) {
        int row_lo = rbase + wm * 64 + mt * 16 + g;
        int row_hi = row_lo + 8;
        float s_lo = (row_lo < n) ? d_s[row_lo] : 0.f;
        float s_hi = (row_hi < n) ? d_s[row_hi] : 0.f;
        #pragma unroll
        for (int nt = 0; nt < 4; nt++) {
            int col = wn * 32 + nt * 8 + tig * 2;
            float b0 = bias[col], b1 = bias[col + 1];
            if (row_lo < n) {
                float2 o = make_float2((acc[mt][nt][0] + b0) * s_lo,
                                       (acc[mt][nt][1] + b1) * s_lo);
                *(float2*)(out + (size_t)row_lo * F + col) = o;
            }
            if (row_hi < n) {
                float2 o = make_float2((acc[mt][nt][2] + b0) * s_hi,
                                       (acc[mt][nt][3] + b1) * s_hi);
                *(float2*)(out + (size_t)row_hi * F + col) = o;
            }
        }
    }
}

// -------- gather: dst[r] = sum over bucket(r) of src[col]  (warp per row) --------
__global__ void gather_kernel(const float* __restrict__ src,
                              float* __restrict__ dst, int n) {
    int warp = (blockIdx.x * blockDim.x + threadIdx.x) >> 5;
    int lane = threadIdx.x & 31;
    int nw = (gridDim.x * blockDim.x) >> 5;
    for (int r = warp; r < n; r += nw) {
        int cnt = d_cnt[r]; if (cnt > CAP) cnt = CAP;
        float4 acc = make_float4(0.f, 0.f, 0.f, 0.f);
        size_t base = (size_t)r << 6;
        for (int i = 0; i < cnt; i++) {
            int c = d_csr[base + i];
            float4 v = ((const float4*)(src + (size_t)c * F))[lane];
            acc.x += v.x; acc.y += v.y; acc.z += v.z; acc.w += v.w;
        }
        ((float4*)(dst + (size_t)r * F))[lane] = acc;
    }
}

// -------- gather + relu + column-sum fusion (never materializes agg2) --------
__global__ void gather_mean_kernel(const float* __restrict__ src, int n) {
    __shared__ float smr[128];
    int t = threadIdx.x;
    if (t < 128) smr[t] = 0.f;
    __syncthreads();
    int warp = (blockIdx.x * blockDim.x + t) >> 5;
    int lane = t & 31;
    int nw = (gridDim.x * blockDim.x) >> 5;
    float4 ps = make_float4(0.f, 0.f, 0.f, 0.f);
    for (int r = warp; r < n; r += nw) {
        int cnt = d_cnt[r]; if (cnt > CAP) cnt = CAP;
        float4 acc = make_float4(0.f, 0.f, 0.f, 0.f);
        size_t base = (size_t)r << 6;
        for (int i = 0; i < cnt; i++) {
            int c = d_csr[base + i];
            float4 v = ((const float4*)(src + (size_t)c * F))[lane];
            acc.x += v.x; acc.y += v.y; acc.z += v.z; acc.w += v.w;
        }
        ps.x += fmaxf(acc.x, 0.f); ps.y += fmaxf(acc.y, 0.f);
        ps.z += fmaxf(acc.z, 0.f); ps.w += fmaxf(acc.w, 0.f);
    }
    atomicAdd(&smr[lane * 4 + 0], ps.x);
    atomicAdd(&smr[lane * 4 + 1], ps.y);
    atomicAdd(&smr[lane * 4 + 2], ps.z);
    atomicAdd(&smr[lane * 4 + 3], ps.w);
    __syncthreads();
    if (t < 128) atomicAdd(&d_gsum[t], smr[t]);
}

// -------- latent head (1 block, 128 threads) --------
__global__ void head_kernel(const float* __restrict__ eps,
                            const float* __restrict__ Wmu, const float* __restrict__ bmu,
                            const float* __restrict__ Wlv, const float* __restrict__ blv,
                            const float* __restrict__ Wn,  const float* __restrict__ bn,
                            const float* __restrict__ We1, const float* __restrict__ be1,
                            const float* __restrict__ We2, const float* __restrict__ be2,
                            float* __restrict__ out, int n, int E) {
    __shared__ float zs[32];
    __shared__ float ehs[128];
    int t = threadIdx.x;
    float invN = 1.0f / (float)n;
    size_t ofs = 16 + (size_t)E * 4;
    if (t < 32) {
        float mu = bmu[t], lv = blv[t];
        for (int c = 0; c < 128; c++) {
            float g = d_gsum[c] * invN;
            mu += g * Wmu[c * 32 + t];
            lv += g * Wlv[c * 32 + t];
        }
        zs[t] = mu + eps[t] * expf(0.5f * lv);
        out[ofs + t] = mu;
        out[ofs + 32 + t] = lv;
    }
    __syncthreads();
    if (t < 16) {
        float v = bn[t];
        for (int j = 0; j < 32; j++) v += zs[j] * Wn[j * 16 + t];
        out[t] = v;
    }
    {
        float v = be1[t];
        for (int k = 0; k < 64; k++) v += zs[k & 31] * We1[k * 128 + t];
        ehs[t] = fmaxf(v, 0.f);
    }
    __syncthreads();
    if (t < 4) {
        float v = be2[t];
        for (int h2 = 0; h2 < 128; h2++) v += ehs[h2] * We2[h2 * 4 + t];
        d_el[t] = v;
    }
}

// -------- broadcast identical edge logits --------
__global__ void bcast_kernel(float* __restrict__ out, int E) {
    int e = blockIdx.x * blockDim.x + threadIdx.x;
    float4 v = *(const float4*)d_el;
    if (e < E) ((float4*)(out + 16))[e] = v;
}

extern "C" void kernel_launch(void* const* d_in, const int* in_sizes, int n_in,
                              void* d_out, int out_size) {
    const float* x   = (const float*)d_in[0];
    const int*   ei  = (const int*)d_in[1];      // int32 (JAX x64 disabled)
    const float* eps = (const float*)d_in[2];
    const float* W1  = (const float*)d_in[3];
    const float* b1  = (const float*)d_in[4];
    const float* W2  = (const float*)d_in[5];
    const float* b2  = (const float*)d_in[6];
    const float* Wmu = (const float*)d_in[7];
    const float* bmu = (const float*)d_in[8];
    const float* Wlv = (const float*)d_in[9];
    const float* blv = (const float*)d_in[10];
    const float* Wn  = (const float*)d_in[11];
    const float* bn  = (const float*)d_in[12];
    const float* We1 = (const float*)d_in[13];
    const float* be1 = (const float*)d_in[14];
    const float* We2 = (const float*)d_in[15];
    const float* be2 = (const float*)d_in[16];
    float* out = (float*)d_out;

    int n = in_sizes[0] / F;       // 500000
    int E = in_sizes[1] / 2;       // 500000

    float* bufA_p = nullptr;
    float* bufB_p = nullptr;
    uint32_t* wf1_p = nullptr;
    uint32_t* wf2_p = nullptr;
    cudaGetSymbolAddress((void**)&bufA_p, d_bufA);
    cudaGetSymbolAddress((void**)&bufB_p, d_bufB);
    cudaGetSymbolAddress((void**)&wf1_p, d_wf1);
    cudaGetSymbolAddress((void**)&wf2_p, d_wf2);

    cudaFuncSetAttribute(gemm_kernel,
                         cudaFuncAttributeMaxDynamicSharedMemorySize, GSM_BYTES);

    int gblocks = (n + 127) / 128;

    zero_kernel<<<(MAXN + 255) / 256, 256>>>();
    fill_kernel<<<(E + 255) / 256, 256>>>(ei, E);
    s_kernel<<<(n + 255) / 256, 256>>>(ei, n, E);
    wprep_kernel<<<8, 512>>>(W1, wf1_p);
    wprep_kernel<<<8, 512>>>(W2, wf2_p);

    // conv1: bufA = (x@W1+b1)*s ; bufB = gather(bufA)
    gemm_kernel<<<gblocks, 256, GSM_BYTES>>>(x, wf1_p, b1, bufA_p, n, 0);
    gather_kernel<<<2048, 256>>>(bufA_p, bufB_p, n);

    // conv2: bufA = (relu(bufB)@W2+b2)*s ; fused gather+relu+colsum
    gemm_kernel<<<gblocks, 256, GSM_BYTES>>>(bufB_p, wf2_p, b2, bufA_p, n, 1);
    gather_mean_kernel<<<2048, 256>>>(bufA_p, n);

    // latent head ; edge-logit broadcast
    head_kernel<<<1, 128>>>(eps, Wmu, bmu, Wlv, blv, Wn, bn, We1, be1, We2, be2,
                            out, n, E);
    bcast_kernel<<<(E + 255) / 256, 256>>>(out, E);
}

// round 15
// speedup vs baseline: 1.2247x; 1.0606x over previous
#include <cuda_runtime.h>
#include <cuda_bf16.h>
#include <cstdint>
#include <cstddef>

#define F 128
#define MAXN 500000
#define CAP 64       // bucket capacity per row (Poisson(1): overflow prob ~0)

// -------- scratch (device globals; no allocation allowed) --------
__device__ __nv_bfloat162 d_bufA[(size_t)MAXN * 64];   // 128 MB (conv1 out, bf16)
__device__ __nv_bfloat162 d_bufB[(size_t)MAXN * 64];   // 128 MB (gathered / conv2 out)
__device__ int   d_csr[(size_t)MAXN * CAP];            // 128 MB padded buckets
__device__ int   d_cnt[MAXN];                          // row degrees
__device__ float d_s[MAXN];
__device__ float d_gsum[F];
__device__ __align__(16) float d_el[4];
__device__ __align__(16) uint32_t d_wf1[65536];   // W1 frags interleaved [H0,H1,L0,L1]
__device__ __align__(16) uint32_t d_wf2[65536];   // W2 frags

// -------- tf32 helpers --------
static __device__ __forceinline__ uint32_t f2tf32(float f) {
    uint32_t r;
    asm("cvt.rna.tf32.f32 %0, %1;" : "=r"(r) : "f"(f));
    return r;
}
// D(16x8,f32) += A(16x8,tf32 row) * B(8x8,tf32 col)
static __device__ __forceinline__ void mma_tf32(float* c, const uint4& a, const uint2& b) {
    asm("mma.sync.aligned.m16n8k8.row.col.f32.tf32.tf32.f32 "
        "{%0,%1,%2,%3}, {%4,%5,%6,%7}, {%8,%9}, {%0,%1,%2,%3};"
        : "+f"(c[0]), "+f"(c[1]), "+f"(c[2]), "+f"(c[3])
        : "r"(a.x), "r"(a.y), "r"(a.z), "r"(a.w), "r"(b.x), "r"(b.y));
}

// -------- zero counters --------
__global__ void zero_kernel() {
    int i = blockIdx.x * blockDim.x + threadIdx.x;
    if (i < MAXN) d_cnt[i] = 0;
    if (i < F) d_gsum[i] = 0.f;
}

// -------- bucket fill: csr[row][p++] = col --------
__global__ void fill_kernel(const int* __restrict__ ei, int E) {
    int e = blockIdx.x * blockDim.x + threadIdx.x;
    if (e < E) {
        int r = ei[e];
        int p = atomicAdd(&d_cnt[r], 1);
        if (p < CAP) d_csr[((size_t)r << 6) + p] = ei[E + e];
    }
}

// -------- per-position norm: s[i] = dis[row[i]] * dis[col[i]] --------
__global__ void s_kernel(const int* __restrict__ ei, int n, int E) {
    int i = blockIdx.x * blockDim.x + threadIdx.x;
    if (i < n) {
        float dr = (float)d_cnt[ei[i]];
        float dc = (float)d_cnt[ei[E + i]];
        float a = dr > 0.f ? rsqrtf(dr) : 0.f;
        float b = dc > 0.f ? rsqrtf(dc) : 0.f;
        d_s[i] = a * b;
    }
}

// -------- one-time W -> fragment-layout transform (grid 8 x 512) --------
// frag = ((nc*16+ks)*32+lp); dst[frag*4+sb]=H, dst[frag*4+2+sb]=L
__global__ void wprep_kernel(const float* __restrict__ W, uint32_t* __restrict__ dst) {
    int lin = blockIdx.x * 512 + threadIdx.x;   // 0..4095
    int k = lin >> 5, q = lin & 31;
    float4 wv4 = *(const float4*)(W + k * F + q * 4);
    int ks = k >> 3, kk = k & 7;
    int btig = kk & 3, sb = kk >> 2;
    int sw = ks & 7;
    float wv[4] = { wv4.x, wv4.y, wv4.z, wv4.w };
    #pragma unroll
    for (int j = 0; j < 4; j++) {
        int c = q * 4 + j;
        int nc = c >> 3, cg = c & 7;
        int lp = (cg * 4 + btig) ^ sw;
        int frag = (nc * 16 + ks) * 32 + lp;
        uint32_t wh = f2tf32(wv[j]);
        float rem = wv[j] - __uint_as_float(wh);
        dst[frag * 4 + sb] = wh;
        dst[frag * 4 + 2 + sb] = f2tf32(rem);
    }
}

// -------- fused tensor-core GEMM: out[i] = (relu?(in[i]) @ W + b) * s[i] --------
// in: fp32 (in_bf16=0) or bf16 (in_bf16=1). out: bf16 (only consumed by
// gather/gather_mean; per-element bf16 rounding is zero-mean and killed by
// the 500k-node mean-pool). Block 128x128, 256 thr, warp tile 64x32,
// B frags via one LDG.128 per (nt,ks), 2 blocks/SM.
// Fragment maps (PTX m16n8k8.tf32): g=lane>>2, tig=lane&3;
//   A: a0=A[g][tig] a1=A[g+8][tig] a2=A[g][tig+4] a3=A[g+8][tig+4]
//   B: b0=B[tig][col_g] b1=B[tig+4][col_g]
//   D: c0=D[g][2tig] c1=D[g][2tig+1] c2=D[g+8][2tig] c3=D[g+8][2tig+1]
#define GSM_BYTES 65536   // A fragments: 8 mc x 16 ks x 32 lanes x 4 u32

__global__ __launch_bounds__(256, 2)
void gemm_kernel(const void* __restrict__ Xin, const uint32_t* __restrict__ wf,
                 const float* __restrict__ bias,
                 __nv_bfloat162* __restrict__ out, int n,
                 int in_bf16, int relu_in) {
    extern __shared__ float smf[];
    uint32_t* smu = (uint32_t*)smf;
    const int tid = threadIdx.x;
    const int w = tid >> 5, l = tid & 31;
    const int wm = w >> 2, wn = w & 3;
    const int g = l >> 2, tig = l & 3;
    const int rbase = blockIdx.x * 128;

    // ---- stage A fragments: 16 per thread (each covers 4 channels of a row)
    #pragma unroll
    for (int it = 0; it < 16; it++) {
        int lin = it * 256 + tid;
        int r = lin >> 5, q = lin & 31;
        int row = rbase + r;
        float4 v = make_float4(0.f, 0.f, 0.f, 0.f);
        if (row < n) {
            if (!in_bf16) {
                v = ((const float4*)Xin)[(size_t)row * 32 + q];
            } else {
                uint2 p = ((const uint2*)Xin)[(size_t)row * 32 + q];
                float2 f0 = __bfloat1622float2(*(const __nv_bfloat162*)&p.x);
                float2 f1 = __bfloat1622float2(*(const __nv_bfloat162*)&p.y);
                v = make_float4(f0.x, f0.y, f1.x, f1.y);
            }
        }
        if (relu_in) {
            v.x = fmaxf(v.x, 0.f); v.y = fmaxf(v.y, 0.f);
            v.z = fmaxf(v.z, 0.f); v.w = fmaxf(v.w, 0.f);
        }
        int mc = r >> 4, gp = r & 15, gg = gp & 7;
        int ks = q >> 1;
        int slot = ((q & 1) << 1) + (gp >> 3);     // {a0,a1,a2,a3} position
        int base16 = (mc * 16 + ks) * 32;
        int sw = ks & 7;
        float vv[4] = { v.x, v.y, v.z, v.w };
        #pragma unroll
        for (int j = 0; j < 4; j++) {
            int lp = (gg * 4 + j) ^ sw;            // j = tig of element k0+j
            smu[(base16 + lp) * 4 + slot] = f2tf32(vv[j]);
        }
    }
    __syncthreads();

    // ---- mainloop: warp tile 64x32 = 4 m-tiles x 4 n-tiles
    float acc[4][4][4];
    #pragma unroll
    for (int mt = 0; mt < 4; mt++)
        #pragma unroll
        for (int nt = 0; nt < 4; nt++)
            #pragma unroll
            for (int j = 0; j < 4; j++) acc[mt][nt][j] = 0.f;

    #pragma unroll 4
    for (int ks = 0; ks < 16; ks++) {
        int lp = l ^ (ks & 7);
        uint4 af[4];
        #pragma unroll
        for (int mt = 0; mt < 4; mt++)
            af[mt] = *(const uint4*)&smu[(((wm * 4 + mt) * 16 + ks) * 32 + lp) * 4];
        uint4 bq[4];
        #pragma unroll
        for (int nt = 0; nt < 4; nt++) {
            int frag = ((wn * 4 + nt) * 16 + ks) * 32 + lp;
            bq[nt] = *(const uint4*)&wf[frag * 4];
        }
        #pragma unroll
        for (int mt = 0; mt < 4; mt++)
            #pragma unroll
            for (int nt = 0; nt < 4; nt++) {
                uint2 bh = make_uint2(bq[nt].x, bq[nt].y);
                uint2 bl = make_uint2(bq[nt].z, bq[nt].w);
                mma_tf32(acc[mt][nt], af[mt], bh);
                mma_tf32(acc[mt][nt], af[mt], bl);
            }
    }

    // ---- epilogue: bias + degree-norm scale, write bf16 pairs
    #pragma unroll
    for (int mt = 0; mt < 4; mt++) {
        int row_lo = rbase + wm * 64 + mt * 16 + g;
        int row_hi = row_lo + 8;
        float s_lo = (row_lo < n) ? d_s[row_lo] : 0.f;
        float s_hi = (row_hi < n) ? d_s[row_hi] : 0.f;
        #pragma unroll
        for (int nt = 0; nt < 4; nt++) {
            int col = wn * 32 + nt * 8 + tig * 2;
            float b0 = bias[col], b1 = bias[col + 1];
            if (row_lo < n) {
                out[((size_t)row_lo * F + col) >> 1] = __floats2bfloat162_rn(
                    (acc[mt][nt][0] + b0) * s_lo, (acc[mt][nt][1] + b1) * s_lo);
            }
            if (row_hi < n) {
                out[((size_t)row_hi * F + col) >> 1] = __floats2bfloat162_rn(
                    (acc[mt][nt][2] + b0) * s_hi, (acc[mt][nt][3] + b1) * s_hi);
            }
        }
    }
}

// -------- gather: dst[r] = sum over bucket(r) of src[col]  (warp per row) --------
// bf16 in/out, fp32 accumulation. Lane covers 4 channels (one uint2).
__global__ void gather_kernel(const __nv_bfloat162* __restrict__ src,
                              __nv_bfloat162* __restrict__ dst, int n) {
    int warp = (blockIdx.x * blockDim.x + threadIdx.x) >> 5;
    int lane = threadIdx.x & 31;
    int nw = (gridDim.x * blockDim.x) >> 5;
    const uint2* s2 = (const uint2*)src;
    uint2* dq = (uint2*)dst;
    for (int r = warp; r < n; r += nw) {
        int cnt = d_cnt[r]; if (cnt > CAP) cnt = CAP;
        float4 acc = make_float4(0.f, 0.f, 0.f, 0.f);
        size_t base = (size_t)r << 6;
        for (int i = 0; i < cnt; i++) {
            int c = d_csr[base + i];
            uint2 p = s2[(size_t)c * 32 + lane];
            float2 f0 = __bfloat1622float2(*(const __nv_bfloat162*)&p.x);
            float2 f1 = __bfloat1622float2(*(const __nv_bfloat162*)&p.y);
            acc.x += f0.x; acc.y += f0.y; acc.z += f1.x; acc.w += f1.y;
        }
        uint2 o;
        __nv_bfloat162 o0 = __floats2bfloat162_rn(acc.x, acc.y);
        __nv_bfloat162 o1 = __floats2bfloat162_rn(acc.z, acc.w);
        o.x = *(const uint32_t*)&o0;
        o.y = *(const uint32_t*)&o1;
        dq[(size_t)r * 32 + lane] = o;
    }
}

// -------- gather + relu + column-sum fusion (never materializes agg2) --------
__global__ void gather_mean_kernel(const __nv_bfloat162* __restrict__ src, int n) {
    __shared__ float smr[128];
    int t = threadIdx.x;
    if (t < 128) smr[t] = 0.f;
    __syncthreads();
    int warp = (blockIdx.x * blockDim.x + t) >> 5;
    int lane = t & 31;
    int nw = (gridDim.x * blockDim.x) >> 5;
    const uint2* s2 = (const uint2*)src;
    float4 ps = make_float4(0.f, 0.f, 0.f, 0.f);
    for (int r = warp; r < n; r += nw) {
        int cnt = d_cnt[r]; if (cnt > CAP) cnt = CAP;
        float4 acc = make_float4(0.f, 0.f, 0.f, 0.f);
        size_t base = (size_t)r << 6;
        for (int i = 0; i < cnt; i++) {
            int c = d_csr[base + i];
            uint2 p = s2[(size_t)c * 32 + lane];
            float2 f0 = __bfloat1622float2(*(const __nv_bfloat162*)&p.x);
            float2 f1 = __bfloat1622float2(*(const __nv_bfloat162*)&p.y);
            acc.x += f0.x; acc.y += f0.y; acc.z += f1.x; acc.w += f1.y;
        }
        ps.x += fmaxf(acc.x, 0.f); ps.y += fmaxf(acc.y, 0.f);
        ps.z += fmaxf(acc.z, 0.f); ps.w += fmaxf(acc.w, 0.f);
    }
    atomicAdd(&smr[lane * 4 + 0], ps.x);
    atomicAdd(&smr[lane * 4 + 1], ps.y);
    atomicAdd(&smr[lane * 4 + 2], ps.z);
    atomicAdd(&smr[lane * 4 + 3], ps.w);
    __syncthreads();
    if (t < 128) atomicAdd(&d_gsum[t], smr[t]);
}

// -------- latent head (1 block, 128 threads) --------
__global__ void head_kernel(const float* __restrict__ eps,
                            const float* __restrict__ Wmu, const float* __restrict__ bmu,
                            const float* __restrict__ Wlv, const float* __restrict__ blv,
                            const float* __restrict__ Wn,  const float* __restrict__ bn,
                            const float* __restrict__ We1, const float* __restrict__ be1,
                            const float* __restrict__ We2, const float* __restrict__ be2,
                            float* __restrict__ out, int n, int E) {
    __shared__ float zs[32];
    __shared__ float ehs[128];
    int t = threadIdx.x;
    float invN = 1.0f / (float)n;
    size_t ofs = 16 + (size_t)E * 4;
    if (t < 32) {
        float mu = bmu[t], lv = blv[t];
        for (int c = 0; c < 128; c++) {
            float g = d_gsum[c] * invN;
            mu += g * Wmu[c * 32 + t];
            lv += g * Wlv[c * 32 + t];
        }
        zs[t] = mu + eps[t] * expf(0.5f * lv);
        out[ofs + t] = mu;
        out[ofs + 32 + t] = lv;
    }
    __syncthreads();
    if (t < 16) {
        float v = bn[t];
        for (int j = 0; j < 32; j++) v += zs[j] * Wn[j * 16 + t];
        out[t] = v;
    }
    {
        float v = be1[t];
        for (int k = 0; k < 64; k++) v += zs[k & 31] * We1[k * 128 + t];
        ehs[t] = fmaxf(v, 0.f);
    }
    __syncthreads();
    if (t < 4) {
        float v = be2[t];
        for (int h2 = 0; h2 < 128; h2++) v += ehs[h2] * We2[h2 * 4 + t];
        d_el[t] = v;
    }
}

// -------- broadcast identical edge logits --------
__global__ void bcast_kernel(float* __restrict__ out, int E) {
    int e = blockIdx.x * blockDim.x + threadIdx.x;
    float4 v = *(const float4*)d_el;
    if (e < E) ((float4*)(out + 16))[e] = v;
}

extern "C" void kernel_launch(void* const* d_in, const int* in_sizes, int n_in,
                              void* d_out, int out_size) {
    const float* x   = (const float*)d_in[0];
    const int*   ei  = (const int*)d_in[1];      // int32 (JAX x64 disabled)
    const float* eps = (const float*)d_in[2];
    const float* W1  = (const float*)d_in[3];
    const float* b1  = (const float*)d_in[4];
    const float* W2  = (const float*)d_in[5];
    const float* b2  = (const float*)d_in[6];
    const float* Wmu = (const float*)d_in[7];
    const float* bmu = (const float*)d_in[8];
    const float* Wlv = (const float*)d_in[9];
    const float* blv = (const float*)d_in[10];
    const float* Wn  = (const float*)d_in[11];
    const float* bn  = (const float*)d_in[12];
    const float* We1 = (const float*)d_in[13];
    const float* be1 = (const float*)d_in[14];
    const float* We2 = (const float*)d_in[15];
    const float* be2 = (const float*)d_in[16];
    float* out = (float*)d_out;

    int n = in_sizes[0] / F;       // 500000
    int E = in_sizes[1] / 2;       // 500000

    __nv_bfloat162* bufA_p = nullptr;
    __nv_bfloat162* bufB_p = nullptr;
    uint32_t* wf1_p = nullptr;
    uint32_t* wf2_p = nullptr;
    cudaGetSymbolAddress((void**)&bufA_p, d_bufA);
    cudaGetSymbolAddress((void**)&bufB_p, d_bufB);
    cudaGetSymbolAddress((void**)&wf1_p, d_wf1);
    cudaGetSymbolAddress((void**)&wf2_p, d_wf2);

    cudaFuncSetAttribute(gemm_kernel,
                         cudaFuncAttributeMaxDynamicSharedMemorySize, GSM_BYTES);

    int gblocks = (n + 127) / 128;

    zero_kernel<<<(MAXN + 255) / 256, 256>>>();
    fill_kernel<<<(E + 255) / 256, 256>>>(ei, E);
    s_kernel<<<(n + 255) / 256, 256>>>(ei, n, E);
    wprep_kernel<<<8, 512>>>(W1, wf1_p);
    wprep_kernel<<<8, 512>>>(W2, wf2_p);

    // conv1: bufA = bf16((x@W1+b1)*s) ; bufB = bf16(gather(bufA))
    gemm_kernel<<<gblocks, 256, GSM_BYTES>>>(x, wf1_p, b1, bufA_p, n, 0, 0);
    gather_kernel<<<2048, 256>>>(bufA_p, bufB_p, n);

    // conv2: bufA = bf16((relu(bufB)@W2+b2)*s) ; fused gather+relu+colsum
    gemm_kernel<<<gblocks, 256, GSM_BYTES>>>(bufB_p, wf2_p, b2, bufA_p, n, 1, 1);
    gather_mean_kernel<<<2048, 256>>>(bufA_p, n);

    // latent head ; edge-logit broadcast
    head_kernel<<<1, 128>>>(eps, Wmu, bmu, Wlv, blv, Wn, bn, We1, be1, We2, be2,
                            out, n, E);
    bcast_kernel<<<(E + 255) / 256, 256>>>(out, E);
}

// round 16
// speedup vs baseline: 1.3901x; 1.1351x over previous
#include <cuda_runtime.h>
#include <cuda_bf16.h>
#include <cstdint>
#include <cstddef>

#define F 128
#define MAXN 500000
#define CAP 64       // bucket capacity per row (Poisson(1): overflow prob ~0)

// -------- scratch (device globals; no allocation allowed) --------
__device__ __nv_bfloat162 d_bufA[(size_t)MAXN * 64];   // 128 MB (conv1 out, bf16)
__device__ __nv_bfloat162 d_bufB[(size_t)MAXN * 64];   // 128 MB (gathered / conv2 out)
__device__ int   d_csr[(size_t)MAXN * CAP];            // 128 MB padded buckets
__device__ int   d_cnt[MAXN];                          // row degrees
__device__ float d_s[MAXN];
__device__ float d_gsum[F];
__device__ __align__(16) float d_el[4];
// W fragments, m16n8k16 bf16, interleaved per slot: [bh0, bh1, bl0, bl1]
// frag = ((nc*8+ks)*32+lane); 16 nc x 8 ks x 32 lanes x 4 u32 = 64 KB each
__device__ __align__(16) uint32_t d_wf1[16384];
__device__ __align__(16) uint32_t d_wf2[16384];

// D(16x8,f32) += A(16x16,bf16 row) * B(16x8,bf16 col)
static __device__ __forceinline__ void mma_bf16(float* c, const uint4& a, const uint2& b) {
    asm("mma.sync.aligned.m16n8k16.row.col.f32.bf16.bf16.f32 "
        "{%0,%1,%2,%3}, {%4,%5,%6,%7}, {%8,%9}, {%0,%1,%2,%3};"
        : "+f"(c[0]), "+f"(c[1]), "+f"(c[2]), "+f"(c[3])
        : "r"(a.x), "r"(a.y), "r"(a.z), "r"(a.w), "r"(b.x), "r"(b.y));
}

// -------- zero counters --------
__global__ void zero_kernel() {
    int i = blockIdx.x * blockDim.x + threadIdx.x;
    if (i < MAXN) d_cnt[i] = 0;
    if (i < F) d_gsum[i] = 0.f;
}

// -------- bucket fill: csr[row][p++] = col --------
__global__ void fill_kernel(const int* __restrict__ ei, int E) {
    int e = blockIdx.x * blockDim.x + threadIdx.x;
    if (e < E) {
        int r = ei[e];
        int p = atomicAdd(&d_cnt[r], 1);
        if (p < CAP) d_csr[((size_t)r << 6) + p] = ei[E + e];
    }
}

// -------- per-position norm: s[i] = dis[row[i]] * dis[col[i]] --------
__global__ void s_kernel(const int* __restrict__ ei, int n, int E) {
    int i = blockIdx.x * blockDim.x + threadIdx.x;
    if (i < n) {
        float dr = (float)d_cnt[ei[i]];
        float dc = (float)d_cnt[ei[E + i]];
        float a = dr > 0.f ? rsqrtf(dr) : 0.f;
        float b = dc > 0.f ? rsqrtf(dc) : 0.f;
        d_s[i] = a * b;
    }
}

// -------- one-time W -> bf16 fragment transform (grid 8 x 512) --------
// For w[k][n]: ks=k>>4, kk=k&15, tig=(kk>>1)&3, hi=kk>>3, half=kk&1;
// lane = (n&7)*4+tig; word = hi (bh) / 2+hi (bl); 16-bit slot = half.
// Split: wh = bf16(w), wl = bf16(w - float(wh)) -> ~16 mantissa bits total.
__global__ void wprep_kernel(const float* __restrict__ W, uint32_t* __restrict__ dst) {
    __nv_bfloat16* d16 = (__nv_bfloat16*)dst;
    int lin = blockIdx.x * 512 + threadIdx.x;   // 0..4095
    int k = lin >> 5, q = lin & 31;
    float4 wv4 = *(const float4*)(W + k * F + q * 4);
    int ks = k >> 4, kk = k & 15;
    int tig = (kk >> 1) & 3, hi = kk >> 3, half = kk & 1;
    float wv[4] = { wv4.x, wv4.y, wv4.z, wv4.w };
    #pragma unroll
    for (int j = 0; j < 4; j++) {
        int c = q * 4 + j;
        int nc = c >> 3, g = c & 7;
        int lane = g * 4 + tig;
        int frag = (nc * 8 + ks) * 32 + lane;
        __nv_bfloat16 wh = __float2bfloat16(wv[j]);
        __nv_bfloat16 wl = __float2bfloat16(wv[j] - __bfloat162float(wh));
        d16[(frag * 4 + hi) * 2 + half] = wh;
        d16[(frag * 4 + 2 + hi) * 2 + half] = wl;
    }
}

// -------- fused tensor-core GEMM: out[i] = (relu?(in[i]) @ W + b) * s[i] --------
// mma.sync m16n8k16 bf16, fp32 accum. Block 128x128, 256 thr (8 warps,
// 2x4 grid, warp tile 64x32). A staged in smem as bf16 fragments (32KB);
// B fragments read from global via ONE LDG.128 per (nt,ks). 2 blocks/SM.
// Fragment maps (PTX m16n8k16): g=lane>>2, tig=lane&3;
//   A: a0={A[g][2tig],A[g][2tig+1]} a1=rows g+8  a2={cols 2tig+8,+9} a3=g+8,hi
//   B: b0={B[2tig][cg],B[2tig+1][cg]} b1={B[2tig+8][cg],B[2tig+9][cg]}
//   D: c0=D[g][2tig] c1=D[g][2tig+1] c2=D[g+8][2tig] c3=D[g+8][2tig+1]
#define GSM_BYTES 32768   // A fragments: 8 mc x 8 ks x 32 lanes x 4 u32

__global__ __launch_bounds__(256, 2)
void gemm_kernel(const void* __restrict__ Xin, const uint32_t* __restrict__ wf,
                 const float* __restrict__ bias,
                 __nv_bfloat162* __restrict__ out, int n,
                 int in_bf16, int relu_in) {
    extern __shared__ float smf[];
    uint32_t* smu = (uint32_t*)smf;
    const int tid = threadIdx.x;
    const int w = tid >> 5, l = tid & 31;
    const int wm = w >> 2, wn = w & 3;
    const int g = l >> 2, tig = l & 3;
    const int rbase = blockIdx.x * 128;

    // ---- stage A fragments: 16 iters, thread covers 4 channels of a row
    #pragma unroll
    for (int it = 0; it < 16; it++) {
        int lin = it * 256 + tid;
        int r = lin >> 5, q = lin & 31;      // channels 4q..4q+3 = pairs 2q, 2q+1
        int row = rbase + r;
        float4 v = make_float4(0.f, 0.f, 0.f, 0.f);
        if (row < n) {
            if (!in_bf16) {
                v = ((const float4*)Xin)[(size_t)row * 32 + q];
            } else {
                uint2 p = ((const uint2*)Xin)[(size_t)row * 32 + q];
                float2 f0 = __bfloat1622float2(*(const __nv_bfloat162*)&p.x);
                float2 f1 = __bfloat1622float2(*(const __nv_bfloat162*)&p.y);
                v = make_float4(f0.x, f0.y, f1.x, f1.y);
            }
        }
        if (relu_in) {
            v.x = fmaxf(v.x, 0.f); v.y = fmaxf(v.y, 0.f);
            v.z = fmaxf(v.z, 0.f); v.w = fmaxf(v.w, 0.f);
        }
        int mc = r >> 4, gp = r & 15, gg = gp & 7;
        int rs = gp >> 3;                    // row-half selector
        #pragma unroll
        for (int pp = 0; pp < 2; pp++) {     // two bf16 pairs in the float4
            int p = 2 * q + pp;              // global pair index 0..63
            int ks = p >> 3, j = p & 7;
            int ptig = j & 3, hi = j >> 2;
            int word = hi * 2 + rs;
            __nv_bfloat162 pk = (pp == 0) ? __floats2bfloat162_rn(v.x, v.y)
                                          : __floats2bfloat162_rn(v.z, v.w);
            smu[((mc * 8 + ks) * 32 + gg * 4 + ptig) * 4 + word] =
                *(const uint32_t*)&pk;
        }
    }
    __syncthreads();

    // ---- mainloop: 8 K-chunks of 16; warp tile 64x32 = 4 mt x 4 nt
    float acc[4][4][4];
    #pragma unroll
    for (int mt = 0; mt < 4; mt++)
        #pragma unroll
        for (int nt = 0; nt < 4; nt++)
            #pragma unroll
            for (int j = 0; j < 4; j++) acc[mt][nt][j] = 0.f;

    #pragma unroll
    for (int ks = 0; ks < 8; ks++) {
        uint4 af[4];
        #pragma unroll
        for (int mt = 0; mt < 4; mt++)
            af[mt] = *(const uint4*)&smu[(((wm * 4 + mt) * 8 + ks) * 32 + l) * 4];
        uint4 bq[4];
        #pragma unroll
        for (int nt = 0; nt < 4; nt++) {
            int frag = ((wn * 4 + nt) * 8 + ks) * 32 + l;
            bq[nt] = *(const uint4*)&wf[frag * 4];
        }
        #pragma unroll
        for (int mt = 0; mt < 4; mt++)
            #pragma unroll
            for (int nt = 0; nt < 4; nt++) {
                uint2 bh = make_uint2(bq[nt].x, bq[nt].y);
                uint2 bl = make_uint2(bq[nt].z, bq[nt].w);
                mma_bf16(acc[mt][nt], af[mt], bh);
                mma_bf16(acc[mt][nt], af[mt], bl);
            }
    }

    // ---- epilogue: bias + degree-norm scale, write bf16 pairs
    #pragma unroll
    for (int mt = 0; mt < 4; mt++) {
        int row_lo = rbase + wm * 64 + mt * 16 + g;
        int row_hi = row_lo + 8;
        float s_lo = (row_lo < n) ? d_s[row_lo] : 0.f;
        float s_hi = (row_hi < n) ? d_s[row_hi] : 0.f;
        #pragma unroll
        for (int nt = 0; nt < 4; nt++) {
            int col = wn * 32 + nt * 8 + tig * 2;
            float b0 = bias[col], b1 = bias[col + 1];
            if (row_lo < n) {
                out[((size_t)row_lo * F + col) >> 1] = __floats2bfloat162_rn(
                    (acc[mt][nt][0] + b0) * s_lo, (acc[mt][nt][1] + b1) * s_lo);
            }
            if (row_hi < n) {
                out[((size_t)row_hi * F + col) >> 1] = __floats2bfloat162_rn(
                    (acc[mt][nt][2] + b0) * s_hi, (acc[mt][nt][3] + b1) * s_hi);
            }
        }
    }
}

// -------- gather: dst[r] = sum over bucket(r) of src[col]  (warp per row) --------
__global__ void gather_kernel(const __nv_bfloat162* __restrict__ src,
                              __nv_bfloat162* __restrict__ dst, int n) {
    int warp = (blockIdx.x * blockDim.x + threadIdx.x) >> 5;
    int lane = threadIdx.x & 31;
    int nw = (gridDim.x * blockDim.x) >> 5;
    const uint2* s2 = (const uint2*)src;
    uint2* dq = (uint2*)dst;
    for (int r = warp; r < n; r += nw) {
        int cnt = d_cnt[r]; if (cnt > CAP) cnt = CAP;
        float4 acc = make_float4(0.f, 0.f, 0.f, 0.f);
        size_t base = (size_t)r << 6;
        for (int i = 0; i < cnt; i++) {
            int c = d_csr[base + i];
            uint2 p = s2[(size_t)c * 32 + lane];
            float2 f0 = __bfloat1622float2(*(const __nv_bfloat162*)&p.x);
            float2 f1 = __bfloat1622float2(*(const __nv_bfloat162*)&p.y);
            acc.x += f0.x; acc.y += f0.y; acc.z += f1.x; acc.w += f1.y;
        }
        uint2 o;
        __nv_bfloat162 o0 = __floats2bfloat162_rn(acc.x, acc.y);
        __nv_bfloat162 o1 = __floats2bfloat162_rn(acc.z, acc.w);
        o.x = *(const uint32_t*)&o0;
        o.y = *(const uint32_t*)&o1;
        dq[(size_t)r * 32 + lane] = o;
    }
}

// -------- gather + relu + column-sum fusion (never materializes agg2) --------
__global__ void gather_mean_kernel(const __nv_bfloat162* __restrict__ src, int n) {
    __shared__ float smr[128];
    int t = threadIdx.x;
    if (t < 128) smr[t] = 0.f;
    __syncthreads();
    int warp = (blockIdx.x * blockDim.x + t) >> 5;
    int lane = t & 31;
    int nw = (gridDim.x * blockDim.x) >> 5;
    const uint2* s2 = (const uint2*)src;
    float4 ps = make_float4(0.f, 0.f, 0.f, 0.f);
    for (int r = warp; r < n; r += nw) {
        int cnt = d_cnt[r]; if (cnt > CAP) cnt = CAP;
        float4 acc = make_float4(0.f, 0.f, 0.f, 0.f);
        size_t base = (size_t)r << 6;
        for (int i = 0; i < cnt; i++) {
            int c = d_csr[base + i];
            uint2 p = s2[(size_t)c * 32 + lane];
            float2 f0 = __bfloat1622float2(*(const __nv_bfloat162*)&p.x);
            float2 f1 = __bfloat1622float2(*(const __nv_bfloat162*)&p.y);
            acc.x += f0.x; acc.y += f0.y; acc.z += f1.x; acc.w += f1.y;
        }
        ps.x += fmaxf(acc.x, 0.f); ps.y += fmaxf(acc.y, 0.f);
        ps.z += fmaxf(acc.z, 0.f); ps.w += fmaxf(acc.w, 0.f);
    }
    atomicAdd(&smr[lane * 4 + 0], ps.x);
    atomicAdd(&smr[lane * 4 + 1], ps.y);
    atomicAdd(&smr[lane * 4 + 2], ps.z);
    atomicAdd(&smr[lane * 4 + 3], ps.w);
    __syncthreads();
    if (t < 128) atomicAdd(&d_gsum[t], smr[t]);
}

// -------- latent head (1 block, 128 threads) --------
__global__ void head_kernel(const float* __restrict__ eps,
                            const float* __restrict__ Wmu, const float* __restrict__ bmu,
                            const float* __restrict__ Wlv, const float* __restrict__ blv,
                            const float* __restrict__ Wn,  const float* __restrict__ bn,
                            const float* __restrict__ We1, const float* __restrict__ be1,
                            const float* __restrict__ We2, const float* __restrict__ be2,
                            float* __restrict__ out, int n, int E) {
    __shared__ float zs[32];
    __shared__ float ehs[128];
    int t = threadIdx.x;
    float invN = 1.0f / (float)n;
    size_t ofs = 16 + (size_t)E * 4;
    if (t < 32) {
        float mu = bmu[t], lv = blv[t];
        for (int c = 0; c < 128; c++) {
            float g = d_gsum[c] * invN;
            mu += g * Wmu[c * 32 + t];
            lv += g * Wlv[c * 32 + t];
        }
        zs[t] = mu + eps[t] * expf(0.5f * lv);
        out[ofs + t] = mu;
        out[ofs + 32 + t] = lv;
    }
    __syncthreads();
    if (t < 16) {
        float v = bn[t];
        for (int j = 0; j < 32; j++) v += zs[j] * Wn[j * 16 + t];
        out[t] = v;
    }
    {
        float v = be1[t];
        for (int k = 0; k < 64; k++) v += zs[k & 31] * We1[k * 128 + t];
        ehs[t] = fmaxf(v, 0.f);
    }
    __syncthreads();
    if (t < 4) {
        float v = be2[t];
        for (int h2 = 0; h2 < 128; h2++) v += ehs[h2] * We2[h2 * 4 + t];
        d_el[t] = v;
    }
}

// -------- broadcast identical edge logits --------
__global__ void bcast_kernel(float* __restrict__ out, int E) {
    int e = blockIdx.x * blockDim.x + threadIdx.x;
    float4 v = *(const float4*)d_el;
    if (e < E) ((float4*)(out + 16))[e] = v;
}

extern "C" void kernel_launch(void* const* d_in, const int* in_sizes, int n_in,
                              void* d_out, int out_size) {
    const float* x   = (const float*)d_in[0];
    const int*   ei  = (const int*)d_in[1];      // int32 (JAX x64 disabled)
    const float* eps = (const float*)d_in[2];
    const float* W1  = (const float*)d_in[3];
    const float* b1  = (const float*)d_in[4];
    const float* W2  = (const float*)d_in[5];
    const float* b2  = (const float*)d_in[6];
    const float* Wmu = (const float*)d_in[7];
    const float* bmu = (const float*)d_in[8];
    const float* Wlv = (const float*)d_in[9];
    const float* blv = (const float*)d_in[10];
    const float* Wn  = (const float*)d_in[11];
    const float* bn  = (const float*)d_in[12];
    const float* We1 = (const float*)d_in[13];
    const float* be1 = (const float*)d_in[14];
    const float* We2 = (const float*)d_in[15];
    const float* be2 = (const float*)d_in[16];
    float* out = (float*)d_out;

    int n = in_sizes[0] / F;       // 500000
    int E = in_sizes[1] / 2;       // 500000

    __nv_bfloat162* bufA_p = nullptr;
    __nv_bfloat162* bufB_p = nullptr;
    uint32_t* wf1_p = nullptr;
    uint32_t* wf2_p = nullptr;
    cudaGetSymbolAddress((void**)&bufA_p, d_bufA);
    cudaGetSymbolAddress((void**)&bufB_p, d_bufB);
    cudaGetSymbolAddress((void**)&wf1_p, d_wf1);
    cudaGetSymbolAddress((void**)&wf2_p, d_wf2);

    cudaFuncSetAttribute(gemm_kernel,
                         cudaFuncAttributeMaxDynamicSharedMemorySize, GSM_BYTES);

    int gblocks = (n + 127) / 128;

    zero_kernel<<<(MAXN + 255) / 256, 256>>>();
    fill_kernel<<<(E + 255) / 256, 256>>>(ei, E);
    s_kernel<<<(n + 255) / 256, 256>>>(ei, n, E);
    wprep_kernel<<<8, 512>>>(W1, wf1_p);
    wprep_kernel<<<8, 512>>>(W2, wf2_p);

    // conv1: bufA = bf16((x@W1+b1)*s) ; bufB = bf16(gather(bufA))
    gemm_kernel<<<gblocks, 256, GSM_BYTES>>>(x, wf1_p, b1, bufA_p, n, 0, 0);
    gather_kernel<<<2048, 256>>>(bufA_p, bufB_p, n);

    // conv2: bufA = bf16((relu(bufB)@W2+b2)*s) ; fused gather+relu+colsum
    gemm_kernel<<<gblocks, 256, GSM_BYTES>>>(bufB_p, wf2_p, b2, bufA_p, n, 1, 1);
    gather_mean_kernel<<<2048, 256>>>(bufA_p, n);

    // latent head ; edge-logit broadcast
    head_kernel<<<1, 128>>>(eps, Wmu, bmu, Wlv, blv, Wn, bn, We1, be1, We2, be2,
                            out, n, E);
    bcast_kernel<<<(E + 255) / 256, 256>>>(out, E);
}

// round 17
// speedup vs baseline: 1.4414x; 1.0369x over previous
#include <cuda_runtime.h>
#include <cuda_bf16.h>
#include <cstdint>
#include <cstddef>

#define F 128
#define MAXN 500000
#define CAP 64       // bucket capacity per row (Poisson(1): overflow prob ~0)

// -------- scratch (device globals; no allocation allowed) --------
__device__ __nv_bfloat162 d_bufA[(size_t)MAXN * 64];   // 128 MB (conv1 out, bf16)
__device__ __nv_bfloat162 d_bufB[(size_t)MAXN * 64];   // 128 MB (gathered / conv2 out)
__device__ int   d_csr[(size_t)MAXN * CAP];            // 128 MB padded buckets
__device__ int   d_cnt[MAXN];                          // row degrees
__device__ float d_s[MAXN];
__device__ float d_gsum[F];
__device__ __align__(16) float d_el[4];
// W fragments, m16n8k16 bf16, interleaved per slot: [bh0, bh1, bl0, bl1]
// frag = ((nc*8+ks)*32+lane); 16 nc x 8 ks x 32 lanes x 4 u32 = 64 KB each
__device__ __align__(16) uint32_t d_wf1[16384];
__device__ __align__(16) uint32_t d_wf2[16384];

// D(16x8,f32) += A(16x16,bf16 row) * B(16x8,bf16 col)
static __device__ __forceinline__ void mma_bf16(float* c, const uint4& a, const uint2& b) {
    asm("mma.sync.aligned.m16n8k16.row.col.f32.bf16.bf16.f32 "
        "{%0,%1,%2,%3}, {%4,%5,%6,%7}, {%8,%9}, {%0,%1,%2,%3};"
        : "+f"(c[0]), "+f"(c[1]), "+f"(c[2]), "+f"(c[3])
        : "r"(a.x), "r"(a.y), "r"(a.z), "r"(a.w), "r"(b.x), "r"(b.y));
}

// -------- zero counters --------
__global__ void zero_kernel() {
    int i = blockIdx.x * blockDim.x + threadIdx.x;
    if (i < MAXN) d_cnt[i] = 0;
    if (i < F) d_gsum[i] = 0.f;
}

// -------- bucket fill: csr[row][p++] = col --------
__global__ void fill_kernel(const int* __restrict__ ei, int E) {
    int e = blockIdx.x * blockDim.x + threadIdx.x;
    if (e < E) {
        int r = ei[e];
        int p = atomicAdd(&d_cnt[r], 1);
        if (p < CAP) d_csr[((size_t)r << 6) + p] = ei[E + e];
    }
}

// -------- per-position norm: s[i] = dis[row[i]] * dis[col[i]] --------
__global__ void s_kernel(const int* __restrict__ ei, int n, int E) {
    int i = blockIdx.x * blockDim.x + threadIdx.x;
    if (i < n) {
        float dr = (float)d_cnt[ei[i]];
        float dc = (float)d_cnt[ei[E + i]];
        float a = dr > 0.f ? rsqrtf(dr) : 0.f;
        float b = dc > 0.f ? rsqrtf(dc) : 0.f;
        d_s[i] = a * b;
    }
}

// -------- one-time W -> bf16 fragment transform (grid 16 x 512, both W) --------
// For w[k][n]: ks=k>>4, kk=k&15, tig=(kk>>1)&3, hi=kk>>3, half=kk&1;
// lane = (n&7)*4+tig; word = hi (bh) / 2+hi (bl); 16-bit slot = half.
// Split: wh = bf16(w), wl = bf16(w - float(wh)) -> ~16 mantissa bits total.
__global__ void wprep_kernel(const float* __restrict__ W1, const float* __restrict__ W2,
                             uint32_t* __restrict__ dst1, uint32_t* __restrict__ dst2) {
    int which = blockIdx.x >> 3;
    const float* W = which ? W2 : W1;
    __nv_bfloat16* d16 = (__nv_bfloat16*)(which ? dst2 : dst1);
    int lin = (blockIdx.x & 7) * 512 + threadIdx.x;   // 0..4095
    int k = lin >> 5, q = lin & 31;
    float4 wv4 = *(const float4*)(W + k * F + q * 4);
    int ks = k >> 4, kk = k & 15;
    int tig = (kk >> 1) & 3, hi = kk >> 3, half = kk & 1;
    float wv[4] = { wv4.x, wv4.y, wv4.z, wv4.w };
    #pragma unroll
    for (int j = 0; j < 4; j++) {
        int c = q * 4 + j;
        int nc = c >> 3, g = c & 7;
        int lane = g * 4 + tig;
        int frag = (nc * 8 + ks) * 32 + lane;
        __nv_bfloat16 wh = __float2bfloat16(wv[j]);
        __nv_bfloat16 wl = __float2bfloat16(wv[j] - __bfloat162float(wh));
        d16[(frag * 4 + hi) * 2 + half] = wh;
        d16[(frag * 4 + 2 + hi) * 2 + half] = wl;
    }
}

// -------- fused tensor-core GEMM: out[i] = (relu?(in[i]) @ W + b) * s[i] --------
// mma.sync m16n8k16 bf16, fp32 accum. Block 128x128, 256 thr (8 warps,
// 2x4 grid, warp tile 64x32). A staged in smem as bf16 fragments (32KB);
// B fragments read from global via ONE LDG.128 per (nt,ks). 2 blocks/SM.
#define GSM_BYTES 32768   // A fragments: 8 mc x 8 ks x 32 lanes x 4 u32

__global__ __launch_bounds__(256, 2)
void gemm_kernel(const void* __restrict__ Xin, const uint32_t* __restrict__ wf,
                 const float* __restrict__ bias,
                 __nv_bfloat162* __restrict__ out, int n,
                 int in_bf16, int relu_in) {
    extern __shared__ float smf[];
    uint32_t* smu = (uint32_t*)smf;
    const int tid = threadIdx.x;
    const int w = tid >> 5, l = tid & 31;
    const int wm = w >> 2, wn = w & 3;
    const int g = l >> 2, tig = l & 3;
    const int rbase = blockIdx.x * 128;

    // ---- stage A fragments: 16 iters, thread covers 4 channels of a row
    #pragma unroll
    for (int it = 0; it < 16; it++) {
        int lin = it * 256 + tid;
        int r = lin >> 5, q = lin & 31;      // channels 4q..4q+3 = pairs 2q, 2q+1
        int row = rbase + r;
        float4 v = make_float4(0.f, 0.f, 0.f, 0.f);
        if (row < n) {
            if (!in_bf16) {
                v = ((const float4*)Xin)[(size_t)row * 32 + q];
            } else {
                uint2 p = ((const uint2*)Xin)[(size_t)row * 32 + q];
                float2 f0 = __bfloat1622float2(*(const __nv_bfloat162*)&p.x);
                float2 f1 = __bfloat1622float2(*(const __nv_bfloat162*)&p.y);
                v = make_float4(f0.x, f0.y, f1.x, f1.y);
            }
        }
        if (relu_in) {
            v.x = fmaxf(v.x, 0.f); v.y = fmaxf(v.y, 0.f);
            v.z = fmaxf(v.z, 0.f); v.w = fmaxf(v.w, 0.f);
        }
        int mc = r >> 4, gp = r & 15, gg = gp & 7;
        int rs = gp >> 3;                    // row-half selector
        #pragma unroll
        for (int pp = 0; pp < 2; pp++) {     // two bf16 pairs in the float4
            int p = 2 * q + pp;              // global pair index 0..63
            int ks = p >> 3, j = p & 7;
            int ptig = j & 3, hi = j >> 2;
            int word = hi * 2 + rs;
            __nv_bfloat162 pk = (pp == 0) ? __floats2bfloat162_rn(v.x, v.y)
                                          : __floats2bfloat162_rn(v.z, v.w);
            smu[((mc * 8 + ks) * 32 + gg * 4 + ptig) * 4 + word] =
                *(const uint32_t*)&pk;
        }
    }
    __syncthreads();

    // ---- mainloop: 8 K-chunks of 16; warp tile 64x32 = 4 mt x 4 nt
    float acc[4][4][4];
    #pragma unroll
    for (int mt = 0; mt < 4; mt++)
        #pragma unroll
        for (int nt = 0; nt < 4; nt++)
            #pragma unroll
            for (int j = 0; j < 4; j++) acc[mt][nt][j] = 0.f;

    #pragma unroll
    for (int ks = 0; ks < 8; ks++) {
        uint4 af[4];
        #pragma unroll
        for (int mt = 0; mt < 4; mt++)
            af[mt] = *(const uint4*)&smu[(((wm * 4 + mt) * 8 + ks) * 32 + l) * 4];
        uint4 bq[4];
        #pragma unroll
        for (int nt = 0; nt < 4; nt++) {
            int frag = ((wn * 4 + nt) * 8 + ks) * 32 + l;
            bq[nt] = *(const uint4*)&wf[frag * 4];
        }
        #pragma unroll
        for (int mt = 0; mt < 4; mt++)
            #pragma unroll
            for (int nt = 0; nt < 4; nt++) {
                uint2 bh = make_uint2(bq[nt].x, bq[nt].y);
                uint2 bl = make_uint2(bq[nt].z, bq[nt].w);
                mma_bf16(acc[mt][nt], af[mt], bh);
                mma_bf16(acc[mt][nt], af[mt], bl);
            }
    }

    // ---- epilogue: bias + degree-norm scale, write bf16 pairs
    #pragma unroll
    for (int mt = 0; mt < 4; mt++) {
        int row_lo = rbase + wm * 64 + mt * 16 + g;
        int row_hi = row_lo + 8;
        float s_lo = (row_lo < n) ? d_s[row_lo] : 0.f;
        float s_hi = (row_hi < n) ? d_s[row_hi] : 0.f;
        #pragma unroll
        for (int nt = 0; nt < 4; nt++) {
            int col = wn * 32 + nt * 8 + tig * 2;
            float b0 = bias[col], b1 = bias[col + 1];
            if (row_lo < n) {
                out[((size_t)row_lo * F + col) >> 1] = __floats2bfloat162_rn(
                    (acc[mt][nt][0] + b0) * s_lo, (acc[mt][nt][1] + b1) * s_lo);
            }
            if (row_hi < n) {
                out[((size_t)row_hi * F + col) >> 1] = __floats2bfloat162_rn(
                    (acc[mt][nt][2] + b0) * s_hi, (acc[mt][nt][3] + b1) * s_hi);
            }
        }
    }
}

// -------- gather helpers: software-pipelined over the cnt->csr->data chain --
// Next row's cnt AND csr quad prefetch at iteration start (csr address is
// independent of cnt) -> per-iteration critical path = data loads only.
static __device__ __forceinline__ void row_accum(const uint2* __restrict__ s2,
                                                 int c, int lane, float4& acc) {
    uint2 p = s2[(size_t)c * 32 + lane];
    float2 f0 = __bfloat1622float2(*(const __nv_bfloat162*)&p.x);
    float2 f1 = __bfloat1622float2(*(const __nv_bfloat162*)&p.y);
    acc.x += f0.x; acc.y += f0.y; acc.z += f1.x; acc.w += f1.y;
}

// -------- gather: dst[r] = sum over bucket(r) of src[col]  (warp per row) --------
__global__ void gather_kernel(const __nv_bfloat162* __restrict__ src,
                              __nv_bfloat162* __restrict__ dst, int n) {
    int warp = (blockIdx.x * blockDim.x + threadIdx.x) >> 5;
    int lane = threadIdx.x & 31;
    int nw = (gridDim.x * blockDim.x) >> 5;
    const uint2* s2 = (const uint2*)src;
    uint2* dq = (uint2*)dst;
    int r = warp;
    if (r >= n) return;
    int cnt = d_cnt[r];
    int4 cq = *(const int4*)&d_csr[(size_t)r << 6];
    while (r < n) {
        int rn = r + nw;
        int cnt_n = 0;
        int4 cq_n = make_int4(0, 0, 0, 0);
        if (rn < n) {
            cnt_n = d_cnt[rn];
            cq_n = *(const int4*)&d_csr[(size_t)rn << 6];
        }
        int cc = cnt > CAP ? CAP : cnt;
        float4 acc = make_float4(0.f, 0.f, 0.f, 0.f);
        if (cc > 0) row_accum(s2, cq.x, lane, acc);
        if (cc > 1) row_accum(s2, cq.y, lane, acc);
        if (cc > 2) row_accum(s2, cq.z, lane, acc);
        if (cc > 3) row_accum(s2, cq.w, lane, acc);
        for (int i = 4; i < cc; i++)
            row_accum(s2, d_csr[((size_t)r << 6) + i], lane, acc);
        uint2 o;
        __nv_bfloat162 o0 = __floats2bfloat162_rn(acc.x, acc.y);
        __nv_bfloat162 o1 = __floats2bfloat162_rn(acc.z, acc.w);
        o.x = *(const uint32_t*)&o0;
        o.y = *(const uint32_t*)&o1;
        dq[(size_t)r * 32 + lane] = o;
        r = rn; cnt = cnt_n; cq = cq_n;
    }
}

// -------- gather + relu + column-sum fusion (never materializes agg2) --------
__global__ void gather_mean_kernel(const __nv_bfloat162* __restrict__ src, int n) {
    __shared__ float smr[128];
    int t = threadIdx.x;
    if (t < 128) smr[t] = 0.f;
    __syncthreads();
    int warp = (blockIdx.x * blockDim.x + t) >> 5;
    int lane = t & 31;
    int nw = (gridDim.x * blockDim.x) >> 5;
    const uint2* s2 = (const uint2*)src;
    float4 ps = make_float4(0.f, 0.f, 0.f, 0.f);
    int r = warp;
    if (r < n) {
        int cnt = d_cnt[r];
        int4 cq = *(const int4*)&d_csr[(size_t)r << 6];
        while (r < n) {
            int rn = r + nw;
            int cnt_n = 0;
            int4 cq_n = make_int4(0, 0, 0, 0);
            if (rn < n) {
                cnt_n = d_cnt[rn];
                cq_n = *(const int4*)&d_csr[(size_t)rn << 6];
            }
            int cc = cnt > CAP ? CAP : cnt;
            float4 acc = make_float4(0.f, 0.f, 0.f, 0.f);
            if (cc > 0) row_accum(s2, cq.x, lane, acc);
            if (cc > 1) row_accum(s2, cq.y, lane, acc);
            if (cc > 2) row_accum(s2, cq.z, lane, acc);
            if (cc > 3) row_accum(s2, cq.w, lane, acc);
            for (int i = 4; i < cc; i++)
                row_accum(s2, d_csr[((size_t)r << 6) + i], lane, acc);
            ps.x += fmaxf(acc.x, 0.f); ps.y += fmaxf(acc.y, 0.f);
            ps.z += fmaxf(acc.z, 0.f); ps.w += fmaxf(acc.w, 0.f);
            r = rn; cnt = cnt_n; cq = cq_n;
        }
    }
    atomicAdd(&smr[lane * 4 + 0], ps.x);
    atomicAdd(&smr[lane * 4 + 1], ps.y);
    atomicAdd(&smr[lane * 4 + 2], ps.z);
    atomicAdd(&smr[lane * 4 + 3], ps.w);
    __syncthreads();
    if (t < 128) atomicAdd(&d_gsum[t], smr[t]);
}

// -------- latent head (1 block, 128 threads) --------
__global__ void head_kernel(const float* __restrict__ eps,
                            const float* __restrict__ Wmu, const float* __restrict__ bmu,
                            const float* __restrict__ Wlv, const float* __restrict__ blv,
                            const float* __restrict__ Wn,  const float* __restrict__ bn,
                            const float* __restrict__ We1, const float* __restrict__ be1,
                            const float* __restrict__ We2, const float* __restrict__ be2,
                            float* __restrict__ out, int n, int E) {
    __shared__ float zs[32];
    __shared__ float ehs[128];
    int t = threadIdx.x;
    float invN = 1.0f / (float)n;
    size_t ofs = 16 + (size_t)E * 4;
    if (t < 32) {
        float mu = bmu[t], lv = blv[t];
        for (int c = 0; c < 128; c++) {
            float g = d_gsum[c] * invN;
            mu += g * Wmu[c * 32 + t];
            lv += g * Wlv[c * 32 + t];
        }
        zs[t] = mu + eps[t] * expf(0.5f * lv);
        out[ofs + t] = mu;
        out[ofs + 32 + t] = lv;
    }
    __syncthreads();
    if (t < 16) {
        float v = bn[t];
        for (int j = 0; j < 32; j++) v += zs[j] * Wn[j * 16 + t];
        out[t] = v;
    }
    {
        float v = be1[t];
        for (int k = 0; k < 64; k++) v += zs[k & 31] * We1[k * 128 + t];
        ehs[t] = fmaxf(v, 0.f);
    }
    __syncthreads();
    if (t < 4) {
        float v = be2[t];
        for (int h2 = 0; h2 < 128; h2++) v += ehs[h2] * We2[h2 * 4 + t];
        d_el[t] = v;
    }
}

// -------- broadcast identical edge logits --------
__global__ void bcast_kernel(float* __restrict__ out, int E) {
    int e = blockIdx.x * blockDim.x + threadIdx.x;
    float4 v = *(const float4*)d_el;
    if (e < E) ((float4*)(out + 16))[e] = v;
}

extern "C" void kernel_launch(void* const* d_in, const int* in_sizes, int n_in,
                              void* d_out, int out_size) {
    const float* x   = (const float*)d_in[0];
    const int*   ei  = (const int*)d_in[1];      // int32 (JAX x64 disabled)
    const float* eps = (const float*)d_in[2];
    const float* W1  = (const float*)d_in[3];
    const float* b1  = (const float*)d_in[4];
    const float* W2  = (const float*)d_in[5];
    const float* b2  = (const float*)d_in[6];
    const float* Wmu = (const float*)d_in[7];
    const float* bmu = (const float*)d_in[8];
    const float* Wlv = (const float*)d_in[9];
    const float* blv = (const float*)d_in[10];
    const float* Wn  = (const float*)d_in[11];
    const float* bn  = (const float*)d_in[12];
    const float* We1 = (const float*)d_in[13];
    const float* be1 = (const float*)d_in[14];
    const float* We2 = (const float*)d_in[15];
    const float* be2 = (const float*)d_in[16];
    float* out = (float*)d_out;

    int n = in_sizes[0] / F;       // 500000
    int E = in_sizes[1] / 2;       // 500000

    __nv_bfloat162* bufA_p = nullptr;
    __nv_bfloat162* bufB_p = nullptr;
    uint32_t* wf1_p = nullptr;
    uint32_t* wf2_p = nullptr;
    cudaGetSymbolAddress((void**)&bufA_p, d_bufA);
    cudaGetSymbolAddress((void**)&bufB_p, d_bufB);
    cudaGetSymbolAddress((void**)&wf1_p, d_wf1);
    cudaGetSymbolAddress((void**)&wf2_p, d_wf2);

    cudaFuncSetAttribute(gemm_kernel,
                         cudaFuncAttributeMaxDynamicSharedMemorySize, GSM_BYTES);

    int gblocks = (n + 127) / 128;

    zero_kernel<<<(MAXN + 255) / 256, 256>>>();
    fill_kernel<<<(E + 255) / 256, 256>>>(ei, E);
    s_kernel<<<(n + 255) / 256, 256>>>(ei, n, E);
    wprep_kernel<<<16, 512>>>(W1, W2, wf1_p, wf2_p);

    // conv1: bufA = bf16((x@W1+b1)*s) ; bufB = bf16(gather(bufA))
    gemm_kernel<<<gblocks, 256, GSM_BYTES>>>(x, wf1_p, b1, bufA_p, n, 0, 0);
    gather_kernel<<<2048, 256>>>(bufA_p, bufB_p, n);

    // conv2: bufA = bf16((relu(bufB)@W2+b2)*s) ; fused gather+relu+colsum
    gemm_kernel<<<gblocks, 256, GSM_BYTES>>>(bufB_p, wf2_p, b2, bufA_p, n, 1, 1);
    gather_mean_kernel<<<2048, 256>>>(bufA_p, n);

    // latent head ; edge-logit broadcast
    head_kernel<<<1, 128>>>(eps, Wmu, bmu, Wlv, blv, Wn, bn, We1, be1, We2, be2,
                            out, n, E);
    bcast_kernel<<<(E + 255) / 256, 256>>>(out, E);
}